// round 13
// baseline (speedup 1.0000x reference)
#include <cuda_runtime.h>
#include <cuda_fp16.h>
#include <cstdint>

// ---------------- problem constants ----------------
#define T_STEPS 16
#define B_SZ    4096
#define D_SZ    512
#define M_SZ    (T_STEPS * B_SZ)      // 65536
#define PLANE   (B_SZ * D_SZ)

// ---------------- GEMM tiling ----------------
#define BM 128
#define BN 128
#define BK 32
#define KITERS (D_SZ / BK)            // 16
#define MTILES (M_SZ / BM)            // 512
#define NTILES (D_SZ / BN)            // 4
#define NSTAGE 3

#define TILE_BYTES  (BM * BK * 2)     // 8192 B (fp16 tile, 64B rows, SW64 swizzle)
#define STAGE_BYTES (4 * TILE_BYTES)  // Ah, Al, Bh, Bl = 32768 B
#define DYN_SMEM    (NSTAGE * STAGE_BYTES)   // 98304 B

// ---------------- scratch ----------------
__device__ float  g_y[(size_t)M_SZ * D_SZ];
__device__ __half g_Wh[D_SZ * D_SZ];
__device__ __half g_Wl[D_SZ * D_SZ];
__device__ float  g_psum[D_SZ * MTILES];   // [feature][mtile] (transposed)
__device__ float  g_psq [D_SZ * MTILES];
__device__ float  g_scale[D_SZ];
__device__ float  g_shift[D_SZ];

// ---------------- PTX helpers ----------------
__device__ __forceinline__ uint32_t smem_u32(const void* p) {
    uint32_t a;
    asm("{ .reg .u64 t; cvta.to.shared.u64 t, %1; cvt.u32.u64 %0, t; }"
        : "=r"(a) : "l"(p));
    return a;
}

#define CP_ASYNC16(dst, src) \
    asm volatile("cp.async.cg.shared.global [%0], [%1], 16;" :: "r"(dst), "l"(src))
#define CP_COMMIT() asm volatile("cp.async.commit_group;")
#define CP_WAIT1()  asm volatile("cp.async.wait_group 1;")

#define LDSM_X4(r0, r1, r2, r3, addr) \
    asm volatile("ldmatrix.sync.aligned.m8n8.x4.shared.b16 {%0,%1,%2,%3}, [%4];" \
        : "=r"(r0), "=r"(r1), "=r"(r2), "=r"(r3) : "r"(addr))

__device__ __forceinline__ void mma16816(float* c, const uint32_t* a,
                                         uint32_t b0, uint32_t b1) {
    asm volatile(
        "mma.sync.aligned.m16n8k16.row.col.f32.f16.f16.f32 "
        "{%0,%1,%2,%3}, {%4,%5,%6,%7}, {%8,%9}, {%0,%1,%2,%3};"
        : "+f"(c[0]), "+f"(c[1]), "+f"(c[2]), "+f"(c[3])
        : "r"(a[0]), "r"(a[1]), "r"(a[2]), "r"(a[3]), "r"(b0), "r"(b1));
}

#define SWZ64(o) ((o) ^ (((o) >> 3) & 0x30))

// ---------------------------------------------------------------------------
// fp32 -> (hi fp16, lo fp16 residual) for 8 values
// ---------------------------------------------------------------------------
__device__ __forceinline__ void split8(const float4 a, const float4 b,
                                       uint4& hi, uint4& lo) {
    half h0 = __float2half_rn(a.x), h1 = __float2half_rn(a.y);
    half h2 = __float2half_rn(a.z), h3 = __float2half_rn(a.w);
    half h4 = __float2half_rn(b.x), h5 = __float2half_rn(b.y);
    half h6 = __float2half_rn(b.z), h7 = __float2half_rn(b.w);
    __half2 p0 = __halves2half2(h0, h1), p1 = __halves2half2(h2, h3);
    __half2 p2 = __halves2half2(h4, h5), p3 = __halves2half2(h6, h7);
    hi = make_uint4(*(uint32_t*)&p0, *(uint32_t*)&p1,
                    *(uint32_t*)&p2, *(uint32_t*)&p3);
    __half2 q0 = __halves2half2(__float2half_rn(a.x - __half2float(h0)),
                                __float2half_rn(a.y - __half2float(h1)));
    __half2 q1 = __halves2half2(__float2half_rn(a.z - __half2float(h2)),
                                __float2half_rn(a.w - __half2float(h3)));
    __half2 q2 = __halves2half2(__float2half_rn(b.x - __half2float(h4)),
                                __float2half_rn(b.y - __half2float(h5)));
    __half2 q3 = __halves2half2(__float2half_rn(b.z - __half2float(h6)),
                                __float2half_rn(b.w - __half2float(h7)));
    lo = make_uint4(*(uint32_t*)&q0, *(uint32_t*)&q1,
                    *(uint32_t*)&q2, *(uint32_t*)&q3);
}

// W-only presplit (3 MB of traffic, ~2 us)
__global__ __launch_bounds__(256)
void split_w_kernel(const float* __restrict__ W) {
    const size_t i = (size_t)(blockIdx.x * 256 + threadIdx.x) * 8;
    float4 a = *(const float4*)(W + i);
    float4 b = *(const float4*)(W + i + 4);
    uint4 hi, lo;
    split8(a, b, hi, lo);
    *(uint4*)((char*)g_Wh + i * 2) = hi;
    *(uint4*)((char*)g_Wl + i * 2) = lo;
}

// ---------------------------------------------------------------------------
// fp16x3 tensor-core GEMM (R10 configuration): in-kernel X split, cp.async W,
// ldmatrix fragments, deterministic BN partials (transposed store layout).
// ---------------------------------------------------------------------------
__global__ __launch_bounds__(256, 2)
void gemm_mma_kernel(const float* __restrict__ X) {
    extern __shared__ char dsm[];

    const int tid  = threadIdx.x;
    const int lane = tid & 31;
    const int warp = tid >> 5;
    const int wm   = warp >> 2;        // 0..1 (64-row slab)
    const int wn   = warp & 3;         // 0..3 (32-col slab)
    const int bm = blockIdx.y * BM;
    const int bn = blockIdx.x * BN;

    const uint32_t smem_base = smem_u32(dsm);

    // ---- loader mapping: thread -> (row, 16-float / 32-half slice) ----
    const int lrow  = tid >> 1;          // 0..127
    const int lc16  = (tid & 1) * 2;     // 16B-half-chunk index 0 or 2
    const float*  pX  = X    + (size_t)(bm + lrow) * D_SZ + lc16 * 8;
    const __half* pWh = g_Wh + (size_t)(bn + lrow) * D_SZ + lc16 * 8;
    const __half* pWl = g_Wl + (size_t)(bn + lrow) * D_SZ + lc16 * 8;
    const uint32_t so  = SWZ64((uint32_t)(lrow * 64 + lc16 * 16));
    const uint32_t so2 = so ^ 16;

    // ---- fragment lane offsets (swizzled, lane-constant) ----
    uint32_t alo[2];
    {
        uint32_t row_off = (lane & 7) + ((lane >> 3) & 1) * 8;
        uint32_t colb = (lane >> 4) * 16;
        #pragma unroll
        for (int ch = 0; ch < 2; ch++) {
            uint32_t o = row_off * 64 + ch * 32 + colb;
            alo[ch] = o ^ (((row_off & 6)) << 3);
        }
    }
    uint32_t blo[2];
    {
        uint32_t row_b = lane & 7;
        uint32_t colb = ((lane >> 3) & 1) * 16;
        uint32_t tsel = (lane < 16) ? 0u : (uint32_t)TILE_BYTES;
        #pragma unroll
        for (int ch = 0; ch < 2; ch++) {
            uint32_t o = row_b * 64 + ch * 32 + colb;
            blo[ch] = (o ^ ((row_b & 6) << 3)) + tsel;
        }
    }

    float acc[4][4][4];
    #pragma unroll
    for (int i = 0; i < 4; i++)
        #pragma unroll
        for (int j = 0; j < 4; j++)
            #pragma unroll
            for (int r = 0; r < 4; r++) acc[i][j][r] = 0.f;

    // ---- B (W halves) stage via cp.async ----
    auto issue_B = [&](int stg) {
        const uint32_t sb = smem_base + (stg % NSTAGE) * STAGE_BYTES;
        const int kt = stg * BK;
        CP_ASYNC16(sb + 2 * TILE_BYTES + so,   pWh + kt);
        CP_ASYNC16(sb + 2 * TILE_BYTES + so2,  pWh + kt + 8);
        CP_ASYNC16(sb + 3 * TILE_BYTES + so,   pWl + kt);
        CP_ASYNC16(sb + 3 * TILE_BYTES + so2,  pWl + kt + 8);
    };

    // ---- A (X) stage: register prefetch -> split -> STS ----
    float4 xp[4];
    auto load_X = [&](int stg) {
        const int kt = stg * BK;
        xp[0] = *(const float4*)(pX + kt);
        xp[1] = *(const float4*)(pX + kt + 4);
        xp[2] = *(const float4*)(pX + kt + 8);
        xp[3] = *(const float4*)(pX + kt + 12);
    };
    auto sts_A = [&](int stg) {
        char* ps = dsm + (stg % NSTAGE) * STAGE_BYTES;
        uint4 hi0, lo0, hi1, lo1;
        split8(xp[0], xp[1], hi0, lo0);
        split8(xp[2], xp[3], hi1, lo1);
        *(uint4*)(ps + so)               = hi0;   // halves 0-7 of slice
        *(uint4*)(ps + so2)              = hi1;   // halves 8-15
        *(uint4*)(ps + TILE_BYTES + so)  = lo0;
        *(uint4*)(ps + TILE_BYTES + so2) = lo1;
    };

    // ---- prologue ----
    load_X(0);
    sts_A(0);              // A stage 0 in SMEM (visible after iter-0 barrier)
    load_X(1);             // prefetch A stage 1 into regs
    issue_B(0); CP_COMMIT();
    issue_B(1); CP_COMMIT();

    #pragma unroll 1
    for (int it = 0; it < KITERS; ++it) {
        CP_WAIT1();                 // B of stage `it` resident
        __syncthreads();            // A STS + B cp.async of stage `it` visible;
                                    // also proves slot (it+2)%3 is reusable

        if (it + 2 < KITERS) issue_B(it + 2);
        CP_COMMIT();                // empty group in tail keeps count valid

        if (it + 1 < KITERS) sts_A(it + 1);   // from regs loaded last iter
        if (it + 2 < KITERS) load_X(it + 2);  // prefetch next (latency spans iter)

        const uint32_t sb  = smem_base + (it % NSTAGE) * STAGE_BYTES;
        const uint32_t sAh = sb + wm * 4096;
        const uint32_t sAl = sAh + TILE_BYTES;
        const uint32_t sB  = sb + 2 * TILE_BYTES + wn * 2048;

        #pragma unroll
        for (int ch = 0; ch < 2; ch++) {
            uint32_t ah[4][4], al[4][4];
            #pragma unroll
            for (int mi = 0; mi < 4; mi++) {
                LDSM_X4(ah[mi][0], ah[mi][1], ah[mi][2], ah[mi][3],
                        sAh + mi * 1024 + alo[ch]);
                LDSM_X4(al[mi][0], al[mi][1], al[mi][2], al[mi][3],
                        sAl + mi * 1024 + alo[ch]);
            }
            #pragma unroll
            for (int nj = 0; nj < 4; nj++) {
                uint32_t b0, b1, b2, b3;   // Bh c, Bh c+8, Bl c, Bl c+8
                LDSM_X4(b0, b1, b2, b3, sB + nj * 512 + blo[ch]);
                // per-acc order hh, hl, lh (bitwise identical to prior rounds)
                #pragma unroll
                for (int mi = 0; mi < 4; mi++)
                    mma16816(acc[mi][nj], ah[mi], b0, b1);
                #pragma unroll
                for (int mi = 0; mi < 4; mi++)
                    mma16816(acc[mi][nj], ah[mi], b2, b3);
                #pragma unroll
                for (int mi = 0; mi < 4; mi++)
                    mma16816(acc[mi][nj], al[mi], b0, b1);
            }
        }
        // single barrier per iter (top of next iteration)
    }
    __syncthreads();

    // ---------------- epilogue: y store (streaming) + BN partials ----------
    const int qrow = lane >> 2;              // 0..7
    const int qcol = (lane & 3) * 2;         // 0,2,4,6
    #pragma unroll
    for (int mi = 0; mi < 4; mi++) {
        #pragma unroll
        for (int nj = 0; nj < 4; nj++) {
            const size_t r0 = (size_t)(bm + wm * 64 + mi * 16 + qrow);
            const int    c0 = bn + wn * 32 + nj * 8 + qcol;
            __stcs((float2*)(g_y + r0 * D_SZ + c0),
                   make_float2(acc[mi][nj][0], acc[mi][nj][1]));
            __stcs((float2*)(g_y + (r0 + 8) * D_SZ + c0),
                   make_float2(acc[mi][nj][2], acc[mi][nj][3]));
        }
    }

    float* red_s = (float*)dsm;                    // 128 cols x 16 slots
    float* red_q = red_s + 128 * 16;
    #pragma unroll
    for (int nj = 0; nj < 4; nj++) {
        #pragma unroll
        for (int par = 0; par < 2; par++) {
            float s = 0.f, q = 0.f;
            #pragma unroll
            for (int mi = 0; mi < 4; mi++) {
                float a0 = acc[mi][nj][par];
                float a1 = acc[mi][nj][2 + par];
                s += a0 + a1;
                q += a0 * a0 + a1 * a1;
            }
            const int c    = wn * 32 + nj * 8 + qcol + par;   // 0..127
            const int slot = wm * 8 + qrow;                    // 0..15
            red_s[c * 16 + slot] = s;
            red_q[c * 16 + slot] = q;
        }
    }
    __syncthreads();
    if (tid < 128) {
        float s = 0.f, q = 0.f;
        #pragma unroll
        for (int k = 0; k < 16; k++) {
            s += red_s[tid * 16 + k];
            q += red_q[tid * 16 + k];
        }
        // transposed layout: [feature][mtile] -> coalesced finalize reads
        g_psum[(size_t)(bn + tid) * MTILES + blockIdx.y] = s;
        g_psq [(size_t)(bn + tid) * MTILES + blockIdx.y] = q;
    }
}

// ---------------------------------------------------------------------------
// finalize BN stats -> per-feature scale/shift.
// Reads are coalesced (consecutive threads -> consecutive mtiles) and the
// summation order is IDENTICAL to R10 (r = t, t+128, t+256, t+384, then the
// same shfl tree) -> bitwise-identical stats.
// ---------------------------------------------------------------------------
__global__ void finalize_kernel(const float* __restrict__ gamma,
                                const float* __restrict__ beta) {
    const int d = blockIdx.x;
    const int t = threadIdx.x;       // 128
    const float* ps = g_psum + (size_t)d * MTILES;
    const float* pq = g_psq  + (size_t)d * MTILES;
    float s = 0.f, q = 0.f;
    #pragma unroll 4
    for (int r = t; r < MTILES; r += 128) {
        s += ps[r];
        q += pq[r];
    }
    #pragma unroll
    for (int o = 16; o; o >>= 1) {
        s += __shfl_xor_sync(0xffffffffu, s, o);
        q += __shfl_xor_sync(0xffffffffu, q, o);
    }
    __shared__ float ss[4], sq[4];
    if ((t & 31) == 0) { ss[t >> 5] = s; sq[t >> 5] = q; }
    __syncthreads();
    if (t == 0) {
        float S = ss[0] + ss[1] + ss[2] + ss[3];
        float Q = sq[0] + sq[1] + sq[2] + sq[3];
        const float inv_n = 1.0f / (float)M_SZ;
        float mean = S * inv_n;
        float var  = Q * inv_n - mean * mean;
        float rstd = rsqrtf(var + 1e-5f);
        float sc = gamma[d] * rstd;
        g_scale[d] = sc;
        g_shift[d] = beta[d] - mean * sc;
    }
}

// ---------------------------------------------------------------------------
// BN apply + residual + LIF scan (R10 form: 1 float4/thread, plain loads)
// ---------------------------------------------------------------------------
__global__ __launch_bounds__(256)
void lif_kernel(const float* __restrict__ x, float* __restrict__ out) {
    const int i4 = blockIdx.x * blockDim.x + threadIdx.x;
    const int d4 = (i4 & 127) * 4;
    const float4 sc = *(const float4*)(g_scale + d4);
    const float4 sh = *(const float4*)(g_shift + d4);
    const float4* yp = (const float4*)g_y;
    const float4* xp = (const float4*)x;
    float4*       op = (float4*)out;

    float4 v = make_float4(0.f, 0.f, 0.f, 0.f);
    #pragma unroll
    for (int t = 0; t < T_STEPS; t++) {
        const size_t off = (size_t)t * (PLANE / 4) + i4;
        float4 y  = yp[off];
        float4 xv = xp[off];
        float4 o;
        {
            float h = fmaf(y.x, sc.x, sh.x) + xv.x;
            v.x = v.x + (h - v.x) * 0.5f;
            bool f = (v.x >= 1.0f); o.x = f ? 1.f : 0.f; v.x = f ? 0.f : v.x;
        }
        {
            float h = fmaf(y.y, sc.y, sh.y) + xv.y;
            v.y = v.y + (h - v.y) * 0.5f;
            bool f = (v.y >= 1.0f); o.y = f ? 1.f : 0.f; v.y = f ? 0.f : v.y;
        }
        {
            float h = fmaf(y.z, sc.z, sh.z) + xv.z;
            v.z = v.z + (h - v.z) * 0.5f;
            bool f = (v.z >= 1.0f); o.z = f ? 1.f : 0.f; v.z = f ? 0.f : v.z;
        }
        {
            float h = fmaf(y.w, sc.w, sh.w) + xv.w;
            v.w = v.w + (h - v.w) * 0.5f;
            bool f = (v.w >= 1.0f); o.w = f ? 1.f : 0.f; v.w = f ? 0.f : v.w;
        }
        op[off] = o;
    }
}

// ---------------------------------------------------------------------------
extern "C" void kernel_launch(void* const* d_in, const int* in_sizes, int n_in,
                              void* d_out, int out_size) {
    const float* x_seq = (const float*)d_in[0];   // [T,B,D]
    const float* W     = (const float*)d_in[1];   // [D,D]
    // d_in[2] = b : cancels inside BatchNorm
    const float* gamma = (const float*)d_in[3];
    const float* beta  = (const float*)d_in[4];
    float* out = (float*)d_out;

    cudaFuncSetAttribute(gemm_mma_kernel,
                         cudaFuncAttributeMaxDynamicSharedMemorySize, DYN_SMEM);

    split_w_kernel<<<(D_SZ * D_SZ / 8) / 256, 256>>>(W);

    dim3 ggrid(NTILES, MTILES);
    gemm_mma_kernel<<<ggrid, 256, DYN_SMEM>>>(x_seq);
    finalize_kernel<<<D_SZ, 128>>>(gamma, beta);
    lif_kernel<<<(PLANE / 4) / 256, 256>>>(x_seq, out);
}

// round 14
// speedup vs baseline: 1.3705x; 1.3705x over previous
#include <cuda_runtime.h>
#include <cuda_fp16.h>
#include <cstdint>

// ---------------- problem constants ----------------
#define T_STEPS 16
#define B_SZ    4096
#define D_SZ    512
#define M_SZ    (T_STEPS * B_SZ)      // 65536
#define PLANE   (B_SZ * D_SZ)

// ---------------- GEMM tiling ----------------
#define BM 128
#define BN 128
#define BK 32
#define KITERS (D_SZ / BK)            // 16
#define MTILES (M_SZ / BM)            // 512
#define NTILES (D_SZ / BN)            // 4
#define NSTAGE 3

#define TILE_BYTES  (BM * BK * 2)     // 8192 B (fp16 tile, 64B rows, SW64 swizzle)
#define STAGE_BYTES (4 * TILE_BYTES)  // Ah, Al, Bh, Bl = 32768 B
#define DYN_SMEM    (NSTAGE * STAGE_BYTES)   // 98304 B

// ---------------- scratch ----------------
__device__ float  g_y[(size_t)M_SZ * D_SZ];
__device__ __half g_Wh[D_SZ * D_SZ];
__device__ __half g_Wl[D_SZ * D_SZ];
__device__ float  g_psum[MTILES * D_SZ];
__device__ float  g_psq [MTILES * D_SZ];
__device__ float  g_scale[D_SZ];
__device__ float  g_shift[D_SZ];

// ---------------- PTX helpers ----------------
__device__ __forceinline__ uint32_t smem_u32(const void* p) {
    uint32_t a;
    asm("{ .reg .u64 t; cvta.to.shared.u64 t, %1; cvt.u32.u64 %0, t; }"
        : "=r"(a) : "l"(p));
    return a;
}

#define CP_ASYNC16(dst, src) \
    asm volatile("cp.async.cg.shared.global [%0], [%1], 16;" :: "r"(dst), "l"(src))
#define CP_COMMIT() asm volatile("cp.async.commit_group;")
#define CP_WAIT1()  asm volatile("cp.async.wait_group 1;")

#define LDSM_X4(r0, r1, r2, r3, addr) \
    asm volatile("ldmatrix.sync.aligned.m8n8.x4.shared.b16 {%0,%1,%2,%3}, [%4];" \
        : "=r"(r0), "=r"(r1), "=r"(r2), "=r"(r3) : "r"(addr))

__device__ __forceinline__ void mma16816(float* c, const uint32_t* a,
                                         uint32_t b0, uint32_t b1) {
    asm volatile(
        "mma.sync.aligned.m16n8k16.row.col.f32.f16.f16.f32 "
        "{%0,%1,%2,%3}, {%4,%5,%6,%7}, {%8,%9}, {%0,%1,%2,%3};"
        : "+f"(c[0]), "+f"(c[1]), "+f"(c[2]), "+f"(c[3])
        : "r"(a[0]), "r"(a[1]), "r"(a[2]), "r"(a[3]), "r"(b0), "r"(b1));
}

#define SWZ64(o) ((o) ^ (((o) >> 3) & 0x30))

// ---------------------------------------------------------------------------
// fp32 -> (hi fp16, lo fp16 residual) for 8 values
// ---------------------------------------------------------------------------
__device__ __forceinline__ void split8(const float4 a, const float4 b,
                                       uint4& hi, uint4& lo) {
    half h0 = __float2half_rn(a.x), h1 = __float2half_rn(a.y);
    half h2 = __float2half_rn(a.z), h3 = __float2half_rn(a.w);
    half h4 = __float2half_rn(b.x), h5 = __float2half_rn(b.y);
    half h6 = __float2half_rn(b.z), h7 = __float2half_rn(b.w);
    __half2 p0 = __halves2half2(h0, h1), p1 = __halves2half2(h2, h3);
    __half2 p2 = __halves2half2(h4, h5), p3 = __halves2half2(h6, h7);
    hi = make_uint4(*(uint32_t*)&p0, *(uint32_t*)&p1,
                    *(uint32_t*)&p2, *(uint32_t*)&p3);
    __half2 q0 = __halves2half2(__float2half_rn(a.x - __half2float(h0)),
                                __float2half_rn(a.y - __half2float(h1)));
    __half2 q1 = __halves2half2(__float2half_rn(a.z - __half2float(h2)),
                                __float2half_rn(a.w - __half2float(h3)));
    __half2 q2 = __halves2half2(__float2half_rn(b.x - __half2float(h4)),
                                __float2half_rn(b.y - __half2float(h5)));
    __half2 q3 = __halves2half2(__float2half_rn(b.z - __half2float(h6)),
                                __float2half_rn(b.w - __half2float(h7)));
    lo = make_uint4(*(uint32_t*)&q0, *(uint32_t*)&q1,
                    *(uint32_t*)&q2, *(uint32_t*)&q3);
}

// W-only presplit (3 MB of traffic, ~2 us)
__global__ __launch_bounds__(256)
void split_w_kernel(const float* __restrict__ W) {
    const size_t i = (size_t)(blockIdx.x * 256 + threadIdx.x) * 8;
    float4 a = *(const float4*)(W + i);
    float4 b = *(const float4*)(W + i + 4);
    uint4 hi, lo;
    split8(a, b, hi, lo);
    *(uint4*)((char*)g_Wh + i * 2) = hi;
    *(uint4*)((char*)g_Wl + i * 2) = lo;
}

// ---------------------------------------------------------------------------
// fp16x3 tensor-core GEMM: in-kernel X split (LDG fp32 -> STS fp16 hi/lo),
// cp.async for W halves, ldmatrix fragments, deterministic BN partials.
// ---------------------------------------------------------------------------
__global__ __launch_bounds__(256, 2)
void gemm_mma_kernel(const float* __restrict__ X) {
    extern __shared__ char dsm[];

    const int tid  = threadIdx.x;
    const int lane = tid & 31;
    const int warp = tid >> 5;
    const int wm   = warp >> 2;        // 0..1 (64-row slab)
    const int wn   = warp & 3;         // 0..3 (32-col slab)
    const int bm = blockIdx.y * BM;
    const int bn = blockIdx.x * BN;

    const uint32_t smem_base = smem_u32(dsm);

    // ---- loader mapping: thread -> (row, 16-float / 32-half slice) ----
    const int lrow  = tid >> 1;          // 0..127
    const int lc16  = (tid & 1) * 2;     // 16B-half-chunk index 0 or 2
    const float*  pX  = X    + (size_t)(bm + lrow) * D_SZ + lc16 * 8;
    const __half* pWh = g_Wh + (size_t)(bn + lrow) * D_SZ + lc16 * 8;
    const __half* pWl = g_Wl + (size_t)(bn + lrow) * D_SZ + lc16 * 8;
    const uint32_t so  = SWZ64((uint32_t)(lrow * 64 + lc16 * 16));
    const uint32_t so2 = so ^ 16;

    // ---- fragment lane offsets (swizzled, lane-constant) ----
    uint32_t alo[2];
    {
        uint32_t row_off = (lane & 7) + ((lane >> 3) & 1) * 8;
        uint32_t colb = (lane >> 4) * 16;
        #pragma unroll
        for (int ch = 0; ch < 2; ch++) {
            uint32_t o = row_off * 64 + ch * 32 + colb;
            alo[ch] = o ^ (((row_off & 6)) << 3);
        }
    }
    uint32_t blo[2];
    {
        uint32_t row_b = lane & 7;
        uint32_t colb = ((lane >> 3) & 1) * 16;
        uint32_t tsel = (lane < 16) ? 0u : (uint32_t)TILE_BYTES;
        #pragma unroll
        for (int ch = 0; ch < 2; ch++) {
            uint32_t o = row_b * 64 + ch * 32 + colb;
            blo[ch] = (o ^ ((row_b & 6) << 3)) + tsel;
        }
    }

    float acc[4][4][4];
    #pragma unroll
    for (int i = 0; i < 4; i++)
        #pragma unroll
        for (int j = 0; j < 4; j++)
            #pragma unroll
            for (int r = 0; r < 4; r++) acc[i][j][r] = 0.f;

    // ---- B (W halves) stage via cp.async ----
    auto issue_B = [&](int stg) {
        const uint32_t sb = smem_base + (stg % NSTAGE) * STAGE_BYTES;
        const int kt = stg * BK;
        CP_ASYNC16(sb + 2 * TILE_BYTES + so,   pWh + kt);
        CP_ASYNC16(sb + 2 * TILE_BYTES + so2,  pWh + kt + 8);
        CP_ASYNC16(sb + 3 * TILE_BYTES + so,   pWl + kt);
        CP_ASYNC16(sb + 3 * TILE_BYTES + so2,  pWl + kt + 8);
    };

    // ---- A (X) stage: register prefetch -> split -> STS ----
    float4 xp[4];
    auto load_X = [&](int stg) {
        const int kt = stg * BK;
        xp[0] = *(const float4*)(pX + kt);
        xp[1] = *(const float4*)(pX + kt + 4);
        xp[2] = *(const float4*)(pX + kt + 8);
        xp[3] = *(const float4*)(pX + kt + 12);
    };
    auto sts_A = [&](int stg) {
        char* ps = dsm + (stg % NSTAGE) * STAGE_BYTES;
        uint4 hi0, lo0, hi1, lo1;
        split8(xp[0], xp[1], hi0, lo0);
        split8(xp[2], xp[3], hi1, lo1);
        *(uint4*)(ps + so)               = hi0;   // halves 0-7 of slice
        *(uint4*)(ps + so2)              = hi1;   // halves 8-15
        *(uint4*)(ps + TILE_BYTES + so)  = lo0;
        *(uint4*)(ps + TILE_BYTES + so2) = lo1;
    };

    // ---- prologue ----
    load_X(0);
    sts_A(0);              // A stage 0 in SMEM (visible after iter-0 barrier)
    load_X(1);             // prefetch A stage 1 into regs
    issue_B(0); CP_COMMIT();
    issue_B(1); CP_COMMIT();

    #pragma unroll 1
    for (int it = 0; it < KITERS; ++it) {
        CP_WAIT1();                 // B of stage `it` resident
        __syncthreads();            // A STS + B cp.async of stage `it` visible;
                                    // also proves slot (it+2)%3 is reusable

        if (it + 2 < KITERS) issue_B(it + 2);
        CP_COMMIT();                // empty group in tail keeps count valid

        if (it + 1 < KITERS) sts_A(it + 1);   // from regs loaded last iter
        if (it + 2 < KITERS) load_X(it + 2);  // prefetch next (latency spans iter)

        const uint32_t sb  = smem_base + (it % NSTAGE) * STAGE_BYTES;
        const uint32_t sAh = sb + wm * 4096;
        const uint32_t sAl = sAh + TILE_BYTES;
        const uint32_t sB  = sb + 2 * TILE_BYTES + wn * 2048;

        #pragma unroll
        for (int ch = 0; ch < 2; ch++) {
            uint32_t ah[4][4], al[4][4];
            #pragma unroll
            for (int mi = 0; mi < 4; mi++) {
                LDSM_X4(ah[mi][0], ah[mi][1], ah[mi][2], ah[mi][3],
                        sAh + mi * 1024 + alo[ch]);
                LDSM_X4(al[mi][0], al[mi][1], al[mi][2], al[mi][3],
                        sAl + mi * 1024 + alo[ch]);
            }
            #pragma unroll
            for (int nj = 0; nj < 4; nj++) {
                uint32_t b0, b1, b2, b3;   // Bh c, Bh c+8, Bl c, Bl c+8
                LDSM_X4(b0, b1, b2, b3, sB + nj * 512 + blo[ch]);
                // per-acc order hh, hl, lh (bitwise identical to prior rounds)
                #pragma unroll
                for (int mi = 0; mi < 4; mi++)
                    mma16816(acc[mi][nj], ah[mi], b0, b1);
                #pragma unroll
                for (int mi = 0; mi < 4; mi++)
                    mma16816(acc[mi][nj], ah[mi], b2, b3);
                #pragma unroll
                for (int mi = 0; mi < 4; mi++)
                    mma16816(acc[mi][nj], al[mi], b0, b1);
            }
        }
        // single barrier per iter (top of next iteration)
    }
    __syncthreads();

    // ---------------- epilogue: y store (streaming) + BN partials ----------
    const int qrow = lane >> 2;              // 0..7
    const int qcol = (lane & 3) * 2;         // 0,2,4,6
    #pragma unroll
    for (int mi = 0; mi < 4; mi++) {
        #pragma unroll
        for (int nj = 0; nj < 4; nj++) {
            const size_t r0 = (size_t)(bm + wm * 64 + mi * 16 + qrow);
            const int    c0 = bn + wn * 32 + nj * 8 + qcol;
            __stcs((float2*)(g_y + r0 * D_SZ + c0),
                   make_float2(acc[mi][nj][0], acc[mi][nj][1]));
            __stcs((float2*)(g_y + (r0 + 8) * D_SZ + c0),
                   make_float2(acc[mi][nj][2], acc[mi][nj][3]));
        }
    }

    float* red_s = (float*)dsm;                    // 128 cols x 16 slots
    float* red_q = red_s + 128 * 16;
    #pragma unroll
    for (int nj = 0; nj < 4; nj++) {
        #pragma unroll
        for (int par = 0; par < 2; par++) {
            float s = 0.f, q = 0.f;
            #pragma unroll
            for (int mi = 0; mi < 4; mi++) {
                float a0 = acc[mi][nj][par];
                float a1 = acc[mi][nj][2 + par];
                s += a0 + a1;
                q += a0 * a0 + a1 * a1;
            }
            const int c    = wn * 32 + nj * 8 + qcol + par;   // 0..127
            const int slot = wm * 8 + qrow;                    // 0..15
            red_s[c * 16 + slot] = s;
            red_q[c * 16 + slot] = q;
        }
    }
    __syncthreads();
    if (tid < 128) {
        float s = 0.f, q = 0.f;
        #pragma unroll
        for (int k = 0; k < 16; k++) {
            s += red_s[tid * 16 + k];
            q += red_q[tid * 16 + k];
        }
        g_psum[blockIdx.y * D_SZ + bn + tid] = s;
        g_psq [blockIdx.y * D_SZ + bn + tid] = q;
    }
}

// ---------------------------------------------------------------------------
// finalize BN stats -> per-feature scale/shift (one block per feature)
// ---------------------------------------------------------------------------
__global__ void finalize_kernel(const float* __restrict__ gamma,
                                const float* __restrict__ beta) {
    const int d = blockIdx.x;
    const int t = threadIdx.x;       // 128
    float s = 0.f, q = 0.f;
    #pragma unroll 4
    for (int r = t; r < MTILES; r += 128) {
        s += g_psum[r * D_SZ + d];
        q += g_psq [r * D_SZ + d];
    }
    #pragma unroll
    for (int o = 16; o; o >>= 1) {
        s += __shfl_xor_sync(0xffffffffu, s, o);
        q += __shfl_xor_sync(0xffffffffu, q, o);
    }
    __shared__ float ss[4], sq[4];
    if ((t & 31) == 0) { ss[t >> 5] = s; sq[t >> 5] = q; }
    __syncthreads();
    if (t == 0) {
        float S = ss[0] + ss[1] + ss[2] + ss[3];
        float Q = sq[0] + sq[1] + sq[2] + sq[3];
        const float inv_n = 1.0f / (float)M_SZ;
        float mean = S * inv_n;
        float var  = Q * inv_n - mean * mean;
        float rstd = rsqrtf(var + 1e-5f);
        float sc = gamma[d] * rstd;
        g_scale[d] = sc;
        g_shift[d] = beta[d] - mean * sc;
    }
}

// ---------------------------------------------------------------------------
// BN apply + residual + LIF scan (vectorized float4, plain loads)
// ---------------------------------------------------------------------------
__global__ __launch_bounds__(256)
void lif_kernel(const float* __restrict__ x, float* __restrict__ out) {
    const int i4 = blockIdx.x * blockDim.x + threadIdx.x;
    const int d4 = (i4 & 127) * 4;
    const float4 sc = *(const float4*)(g_scale + d4);
    const float4 sh = *(const float4*)(g_shift + d4);
    const float4* yp = (const float4*)g_y;
    const float4* xp = (const float4*)x;
    float4*       op = (float4*)out;

    float4 v = make_float4(0.f, 0.f, 0.f, 0.f);
    #pragma unroll
    for (int t = 0; t < T_STEPS; t++) {
        const size_t off = (size_t)t * (PLANE / 4) + i4;
        float4 y  = yp[off];
        float4 xv = xp[off];
        float4 o;
        {
            float h = fmaf(y.x, sc.x, sh.x) + xv.x;
            v.x = v.x + (h - v.x) * 0.5f;
            bool f = (v.x >= 1.0f); o.x = f ? 1.f : 0.f; v.x = f ? 0.f : v.x;
        }
        {
            float h = fmaf(y.y, sc.y, sh.y) + xv.y;
            v.y = v.y + (h - v.y) * 0.5f;
            bool f = (v.y >= 1.0f); o.y = f ? 1.f : 0.f; v.y = f ? 0.f : v.y;
        }
        {
            float h = fmaf(y.z, sc.z, sh.z) + xv.z;
            v.z = v.z + (h - v.z) * 0.5f;
            bool f = (v.z >= 1.0f); o.z = f ? 1.f : 0.f; v.z = f ? 0.f : v.z;
        }
        {
            float h = fmaf(y.w, sc.w, sh.w) + xv.w;
            v.w = v.w + (h - v.w) * 0.5f;
            bool f = (v.w >= 1.0f); o.w = f ? 1.f : 0.f; v.w = f ? 0.f : v.w;
        }
        op[off] = o;
    }
}

// ---------------------------------------------------------------------------
extern "C" void kernel_launch(void* const* d_in, const int* in_sizes, int n_in,
                              void* d_out, int out_size) {
    const float* x_seq = (const float*)d_in[0];   // [T,B,D]
    const float* W     = (const float*)d_in[1];   // [D,D]
    // d_in[2] = b : cancels inside BatchNorm
    const float* gamma = (const float*)d_in[3];
    const float* beta  = (const float*)d_in[4];
    float* out = (float*)d_out;

    cudaFuncSetAttribute(gemm_mma_kernel,
                         cudaFuncAttributeMaxDynamicSharedMemorySize, DYN_SMEM);

    split_w_kernel<<<(D_SZ * D_SZ / 8) / 256, 256>>>(W);

    dim3 ggrid(NTILES, MTILES);
    gemm_mma_kernel<<<ggrid, 256, DYN_SMEM>>>(x_seq);
    finalize_kernel<<<D_SZ, 128>>>(gamma, beta);
    lif_kernel<<<(PLANE / 4) / 256, 256>>>(x_seq, out);
}